// round 4
// baseline (speedup 1.0000x reference)
#include <cuda_runtime.h>

#define SEQ   4096
#define BATCH 64
#define INP   64
#define HID   256
#define G3    768      // 3*HID
#define NCTA  128      // persistent scan CTAs (<= 148 SMs -> co-resident)

// Scratch (static device allocations are the sanctioned workaround)
__device__ float d_xg[(size_t)SEQ * G3 * BATCH];   // [s][g][b]
__device__ float d_hs[(size_t)SEQ * HID * BATCH];  // [s][j][b]
__device__ unsigned int d_tag[NCTA * 8];           // 32B-strided monotonic epochs

__device__ __forceinline__ void fma2(unsigned long long& acc,
                                     unsigned long long a,
                                     unsigned long long b) {
    asm("fma.rn.f32x2 %0, %1, %2, %0;" : "+l"(acc) : "l"(a), "l"(b));
}

// ---------------------------------------------------------------------------
// Kernel A: xg[s][g][b] = sum_i x[s][b][i] * w_ih[g][i] + b_ih[g]
// ---------------------------------------------------------------------------
__global__ void __launch_bounds__(256) xg_kernel(const float* __restrict__ x,
                                                 const float* __restrict__ w_ih,
                                                 const float* __restrict__ b_ih) {
    __shared__ float xs[INP][BATCH + 1];
    __shared__ float ws[64][INP];
    const int s   = blockIdx.x;
    const int g0  = blockIdx.y * 64;
    const int tid = threadIdx.x;

    const float* xsrc = x + (size_t)s * BATCH * INP;
    for (int idx = tid; idx < BATCH * INP; idx += 256) {
        int b = idx >> 6, i = idx & 63;
        xs[i][b] = xsrc[idx];
    }
    const float* wsrc = w_ih + (size_t)g0 * INP;
    for (int idx = tid; idx < 64 * INP; idx += 256)
        ws[idx >> 6][idx & 63] = wsrc[idx];
    __syncthreads();

    const int b  = tid & 63;
    const int gg = tid >> 6;
    float xr[INP];
#pragma unroll
    for (int i = 0; i < INP; i++) xr[i] = xs[i][b];

    float acc[16];
#pragma unroll
    for (int u = 0; u < 16; u++) acc[u] = 0.0f;
    const int gb = gg * 16;
#pragma unroll
    for (int i4 = 0; i4 < INP / 4; i4++) {
#pragma unroll
        for (int u = 0; u < 16; u++) {
            float4 w4 = *(const float4*)&ws[gb + u][i4 * 4];
            acc[u] += w4.x * xr[i4 * 4 + 0];
            acc[u] += w4.y * xr[i4 * 4 + 1];
            acc[u] += w4.z * xr[i4 * 4 + 2];
            acc[u] += w4.w * xr[i4 * 4 + 3];
        }
    }
    float* dst = d_xg + ((size_t)s * G3 + g0) * BATCH;
#pragma unroll
    for (int u = 0; u < 16; u++) {
        int gl = gb + u;
        __stcs(&dst[(size_t)gl * BATCH + b], acc[u] + b_ih[g0 + gl]);
    }
}

// ---------------------------------------------------------------------------
// Kernel B: persistent GRU scan with CHUNKED ready-order consumption.
// 128 CTAs x 256 threads. CTA c owns hidden units j0=2c, j0+1 (6 gate rows).
// K=256 split into 8 chunks of 32k (16 producer CTAs each). Per chunk:
// poll those 16 tags, acquire, accumulate. Chunk order starts at own chunk
// (always ready) so straggler producers gate only the last 1/8 of work.
// ---------------------------------------------------------------------------
__global__ void __launch_bounds__(256) scan_kernel(const float* __restrict__ w_hh,
                                                   const float* __restrict__ b_hh) {
    __shared__ __align__(16) float2 ws2[6][HID];   // {w,w} duplicated pairs
    __shared__ float red[8][6][BATCH];             // [ksub][row][b]
    const int c   = blockIdx.x;
    const int j0  = c * 2;
    const int tid = threadIdx.x;

    for (int idx = tid; idx < 6 * HID; idx += 256) {
        int r  = idx >> 8;
        int k  = idx & 255;
        int jj = r / 3, gam = r % 3;
        float w = w_hh[((size_t)gam * HID + j0 + jj) * HID + k];
        ws2[r][k] = make_float2(w, w);
    }

    // GEMM mapping: row-half rh (3 rows), k-sub ks (4 k per chunk), batch quad bq
    const int rh    = tid >> 7;            // 0/1 -> rows rh*3 .. rh*3+2
    const int ks    = (tid >> 4) & 7;      // 0..7
    const int bq    = tid & 15;            // batches bq*4 .. bq*4+3
    const int rbase = rh * 3;
    const int lane  = tid & 31;
    const int chunk0 = c >> 4;             // own chunk first

    // Pointwise mapping (first 128 threads)
    const int pb  = tid & 63;
    const int pjj = (tid >> 6) & 1;
    const int pj  = j0 + pjj;
    const float bh_r = b_hh[pj];
    const float bh_z = b_hh[HID + pj];
    const float bh_n = b_hh[2 * HID + pj];

    float h_prev = 0.0f;                   // own (pj,pb) state (tid<128)
    __syncthreads();

    for (int t = 0; t < SEQ; t++) {
        // Prefetch this step's input-side gates (independent of tags).
        float xrv = 0.f, xzv = 0.f, xnv = 0.f;
        if (tid < 128) {
            const size_t xoff = (size_t)t * G3 * BATCH;
            xrv = __ldcs(&d_xg[xoff + (size_t)pj * BATCH + pb]);
            xzv = __ldcs(&d_xg[xoff + (size_t)(HID + pj) * BATCH + pb]);
            xnv = __ldcs(&d_xg[xoff + (size_t)(2 * HID + pj) * BATCH + pb]);
        }

        unsigned long long acc[3][2];
#pragma unroll
        for (int r = 0; r < 3; r++) { acc[r][0] = 0ull; acc[r][1] = 0ull; }

        if (t > 0) {
            const float* hp = d_hs + (size_t)(t - 1) * HID * BATCH;
            const unsigned int tt = (unsigned int)t;
#pragma unroll
            for (int i = 0; i < 8; i++) {
                const int m = (chunk0 + i) & 7;
                // Poll the 16 producers of chunk m (lanes watch one tag each).
                const unsigned int* tagp = &d_tag[(m * 16 + (lane & 15)) * 8];
                bool ready;
                do {
                    unsigned int v;
                    asm volatile("ld.relaxed.gpu.global.u32 %0, [%1];"
                                 : "=r"(v) : "l"(tagp) : "memory");
                    ready = __all_sync(0xFFFFFFFFu, v >= tt);
                } while (!ready);
                asm volatile("fence.acq_rel.gpu;" ::: "memory");

                const int k = m * 32 + ks * 4;
                ulonglong2 H0 = *(const ulonglong2*)&hp[(k + 0) * BATCH + bq * 4];
                ulonglong2 H1 = *(const ulonglong2*)&hp[(k + 1) * BATCH + bq * 4];
                ulonglong2 H2 = *(const ulonglong2*)&hp[(k + 2) * BATCH + bq * 4];
                ulonglong2 H3 = *(const ulonglong2*)&hp[(k + 3) * BATCH + bq * 4];
#pragma unroll
                for (int r = 0; r < 3; r++) {
                    ulonglong2 W01 = *(const ulonglong2*)&ws2[rbase + r][k];
                    ulonglong2 W23 = *(const ulonglong2*)&ws2[rbase + r][k + 2];
                    fma2(acc[r][0], W01.x, H0.x); fma2(acc[r][1], W01.x, H0.y);
                    fma2(acc[r][0], W01.y, H1.x); fma2(acc[r][1], W01.y, H1.y);
                    fma2(acc[r][0], W23.x, H2.x); fma2(acc[r][1], W23.x, H2.y);
                    fma2(acc[r][0], W23.y, H3.x); fma2(acc[r][1], W23.y, H3.y);
                }
            }
        }
#pragma unroll
        for (int r = 0; r < 3; r++) {
            float2 a0 = *(float2*)&acc[r][0];
            float2 a1 = *(float2*)&acc[r][1];
            red[ks][rbase + r][bq * 4 + 0] = a0.x;
            red[ks][rbase + r][bq * 4 + 1] = a0.y;
            red[ks][rbase + r][bq * 4 + 2] = a1.x;
            red[ks][rbase + r][bq * 4 + 3] = a1.y;
        }
        __syncthreads();

        if (tid < 128) {
            // pointwise GRU update (torch: n = tanh(xn + r*(hn + bhh_n)))
            float sr = 0.0f, sz = 0.0f, sn = 0.0f;
#pragma unroll
            for (int q = 0; q < 8; q++) {
                sr += red[q][pjj * 3 + 0][pb];
                sz += red[q][pjj * 3 + 1][pb];
                sn += red[q][pjj * 3 + 2][pb];
            }
            const float rg = 1.0f / (1.0f + __expf(-(xrv + sr + bh_r)));
            const float zg = 1.0f / (1.0f + __expf(-(xzv + sz + bh_z)));
            const float ng = tanhf(xnv + rg * (sn + bh_n));
            const float hnew = (1.0f - zg) * ng + zg * h_prev;
            h_prev = hnew;
            d_hs[((size_t)t * HID + pj) * BATCH + pb] = hnew;
        }

        __syncthreads();                   // CTA's h slice fully stored
        if (tid == 0)                      // publish epoch with release semantics
            asm volatile("st.release.gpu.global.u32 [%0], %1;"
                         :: "l"(&d_tag[c * 8]), "r"((unsigned)(t + 1)) : "memory");
    }
}

// ---------------------------------------------------------------------------
// Kernel C: out[s][b] = sum_j fc_w[j] * hs[s][j][b] + fc_b ; re-arms tags.
// ---------------------------------------------------------------------------
__global__ void __launch_bounds__(256) fc_kernel(const float* __restrict__ fc_w,
                                                 const float* __restrict__ fc_b,
                                                 float* __restrict__ out) {
    __shared__ float wsh[HID];
    __shared__ float red[4][BATCH];
    const int s   = blockIdx.x;
    const int tid = threadIdx.x;
    if (s == 0 && tid < NCTA) d_tag[tid * 8] = 0u;   // re-arm for next replay
    if (tid < HID) wsh[tid] = fc_w[tid];
    __syncthreads();
    const int b  = tid & 63;
    const int jc = tid >> 6;
    const float* hp = d_hs + (size_t)s * HID * BATCH;
    float sum = 0.0f;
#pragma unroll 8
    for (int j = jc * 64; j < jc * 64 + 64; j++)
        sum += wsh[j] * __ldcs(&hp[(size_t)j * BATCH + b]);
    red[jc][b] = sum;
    __syncthreads();
    if (tid < BATCH)
        out[(size_t)s * BATCH + tid] =
            red[0][tid] + red[1][tid] + red[2][tid] + red[3][tid] + fc_b[0];
}

extern "C" void kernel_launch(void* const* d_in, const int* in_sizes, int n_in,
                              void* d_out, int out_size) {
    const float* x    = (const float*)d_in[0];
    const float* w_ih = (const float*)d_in[1];
    const float* w_hh = (const float*)d_in[2];
    const float* b_ih = (const float*)d_in[3];
    const float* b_hh = (const float*)d_in[4];
    const float* fc_w = (const float*)d_in[5];
    const float* fc_b = (const float*)d_in[6];
    float* out = (float*)d_out;

    dim3 ga(SEQ, G3 / 64);
    xg_kernel<<<ga, 256>>>(x, w_ih, b_ih);          // input-side gate projections
    scan_kernel<<<NCTA, 256>>>(w_hh, b_hh);         // chunked dataflow scan
    fc_kernel<<<SEQ, 256>>>(fc_w, fc_b, out);       // output head + tag re-arm
}

// round 5
// speedup vs baseline: 4.5952x; 4.5952x over previous
#include <cuda_runtime.h>

#define SEQ   4096
#define BATCH 64
#define INP   64
#define HID   256
#define G3    768
#define BG    16          // batch groups (4 batches each)
#define HG    8           // hidden groups (32 units each)
#define NCTA  (BG*HG)     // 128 scan CTAs

// Scratch (static device allocations are the sanctioned workaround)
__device__ float d_xg[(size_t)SEQ * G3 * BATCH];        // [s][g][b]
__device__ float d_hbuf[2 * BG * HID * 4];              // [par][bg][u][b4] double buffer
__device__ float d_fcp[(size_t)NCTA * SEQ * 4];         // [(bg*8+hg)][t][b4] fc partials
__device__ unsigned int d_tag[NCTA * 8];                // 32B-strided monotonic epochs

__device__ __forceinline__ void fma2(unsigned long long& acc,
                                     unsigned long long a,
                                     unsigned long long b) {
    asm("fma.rn.f32x2 %0, %1, %2, %0;" : "+l"(acc) : "l"(a), "l"(b));
}
__device__ __forceinline__ unsigned long long pk(float a, float b) {
    unsigned long long r;
    asm("mov.b64 %0, {%1, %2};" : "=l"(r) : "f"(a), "f"(b));
    return r;
}
__device__ __forceinline__ float2 unpk(unsigned long long v) {
    float lo, hi;
    asm("mov.b64 {%0, %1}, %2;" : "=f"(lo), "=f"(hi) : "l"(v));
    return make_float2(lo, hi);
}

// ---------------------------------------------------------------------------
// Kernel A: xg[s][g][b] = sum_i x[s][b][i] * w_ih[g][i] + b_ih[g]
// ---------------------------------------------------------------------------
__global__ void __launch_bounds__(256) xg_kernel(const float* __restrict__ x,
                                                 const float* __restrict__ w_ih,
                                                 const float* __restrict__ b_ih) {
    __shared__ float xs[INP][BATCH + 1];
    __shared__ float ws[64][INP];
    const int s   = blockIdx.x;
    const int g0  = blockIdx.y * 64;
    const int tid = threadIdx.x;

    const float* xsrc = x + (size_t)s * BATCH * INP;
    for (int idx = tid; idx < BATCH * INP; idx += 256) {
        int b = idx >> 6, i = idx & 63;
        xs[i][b] = xsrc[idx];
    }
    const float* wsrc = w_ih + (size_t)g0 * INP;
    for (int idx = tid; idx < 64 * INP; idx += 256)
        ws[idx >> 6][idx & 63] = wsrc[idx];
    __syncthreads();

    const int b  = tid & 63;
    const int gg = tid >> 6;
    float xr[INP];
#pragma unroll
    for (int i = 0; i < INP; i++) xr[i] = xs[i][b];

    float acc[16];
#pragma unroll
    for (int u = 0; u < 16; u++) acc[u] = 0.0f;
    const int gb = gg * 16;
#pragma unroll
    for (int i4 = 0; i4 < INP / 4; i4++) {
#pragma unroll
        for (int u = 0; u < 16; u++) {
            float4 w4 = *(const float4*)&ws[gb + u][i4 * 4];
            acc[u] += w4.x * xr[i4 * 4 + 0];
            acc[u] += w4.y * xr[i4 * 4 + 1];
            acc[u] += w4.z * xr[i4 * 4 + 2];
            acc[u] += w4.w * xr[i4 * 4 + 3];
        }
    }
    float* dst = d_xg + ((size_t)s * G3 + g0) * BATCH;
#pragma unroll
    for (int u = 0; u < 16; u++) {
        int gl = gb + u;
        __stcs(&dst[(size_t)gl * BATCH + b], acc[u] + b_ih[g0 + gl]);
    }
}

// ---------------------------------------------------------------------------
// Kernel B: batch-tiled persistent GRU scan.
// CTA (bg,hg): 4 batches x 32 hidden units. w_hh slice register-resident
// (96 floats/thread). Sync fan-in = 8 CTAs per independent batch column.
// h exchanged via tiny L2 double buffer (__ldcg). FC folded in as partials.
// Thread map: rg = tid>>3 (hidden unit j, 0..31), kg = tid&7 (k strip).
// k strip interleaved: k = i*32 + kg*4 + {0..3}, i = 0..7 (conflict-free LDS).
// fma2 lanes = (k even, k odd) pairs; kg-reduce via 3 shuffle rounds.
// ---------------------------------------------------------------------------
__global__ void __launch_bounds__(256, 1) scan_kernel(const float* __restrict__ w_hh,
                                                      const float* __restrict__ b_hh,
                                                      const float* __restrict__ fc_w) {
    __shared__ float hsm[4][HID];          // [b_local][k]
    __shared__ float sout[3][4][32];       // [gate][b_local][j]
    __shared__ float fcred[4][32];         // [b_local][j]

    const int c   = blockIdx.x;
    const int bg  = c & (BG - 1);
    const int hg  = c >> 4;
    const int tid = threadIdx.x;
    const int rg  = tid >> 3;              // hidden unit j (0..31)
    const int kg  = tid & 7;               // k strip

    // Register-resident weights: w2u[g][2i+p] covers k = i*32+kg*4 (+2p)
    unsigned long long w2u[3][16];
#pragma unroll
    for (int g = 0; g < 3; g++)
#pragma unroll
        for (int i = 0; i < 8; i++) {
            const float4 v = *(const float4*)&w_hh[((size_t)(g * HID + hg * 32 + rg)) * HID
                                                   + i * 32 + kg * 4];
            w2u[g][i * 2 + 0] = pk(v.x, v.y);
            w2u[g][i * 2 + 1] = pk(v.z, v.w);
        }

    // Pointwise mapping (tid < 128): (j, b_local)
    const int pj   = tid >> 2;
    const int pb   = tid & 3;
    const int u    = hg * 32 + pj;         // hidden unit index
    const int gbat = bg * 4 + pb;          // global batch
    const float bh_r = b_hh[u];
    const float bh_z = b_hh[HID + u];
    const float bh_n = b_hh[2 * HID + u];
    const float fw   = fc_w[u];

    float h_prev = 0.0f;                   // own (u, gbat) state
    __syncthreads();

    for (int t = 0; t < SEQ; t++) {
        // Prefetch input-side gates (fresh addresses, independent of tags)
        float xrv = 0.f, xzv = 0.f, xnv = 0.f;
        if (tid < 128) {
            const size_t base = ((size_t)t * G3 + u) * BATCH + gbat;
            xrv = __ldcs(&d_xg[base]);
            xzv = __ldcs(&d_xg[base + (size_t)HID * BATCH]);
            xnv = __ldcs(&d_xg[base + (size_t)2 * HID * BATCH]);
        }

        unsigned long long acc[3][4];
#pragma unroll
        for (int g = 0; g < 3; g++)
#pragma unroll
            for (int b = 0; b < 4; b++) acc[g][b] = 0ull;

        if (t > 0) {
            // Poll the 8 column tags (warp 0; lanes mirror mod 8)
            if (tid < 32) {
                const unsigned int* tp = &d_tag[(bg * HG + (tid & 7)) * 8];
                const unsigned int tt = (unsigned int)t;
                bool ok;
                do {
                    unsigned int v;
                    asm volatile("ld.acquire.gpu.global.u32 %0, [%1];"
                                 : "=r"(v) : "l"(tp) : "memory");
                    ok = __all_sync(0xFFFFFFFFu, v >= tt);
                } while (!ok);
            }
            __syncthreads();

            // Gather h(t-1) for our 4 batches: 4KB from L2 (bypass L1: reused addrs)
            {
                const float4 hv = __ldcg((const float4*)&d_hbuf[
                    (((t - 1) & 1) * BG + bg) * HID * 4 + tid * 4]);
                hsm[0][tid] = hv.x;
                hsm[1][tid] = hv.y;
                hsm[2][tid] = hv.z;
                hsm[3][tid] = hv.w;
            }
            __syncthreads();

            // MAC: 192 fma2/thread, LDS.128 conflict-free (kg*16B strips)
#pragma unroll
            for (int b = 0; b < 4; b++) {
#pragma unroll
                for (int i = 0; i < 8; i++) {
                    const ulonglong2 hh = *(const ulonglong2*)&hsm[b][i * 32 + kg * 4];
#pragma unroll
                    for (int g = 0; g < 3; g++) {
                        fma2(acc[g][b], w2u[g][i * 2 + 0], hh.x);
                        fma2(acc[g][b], w2u[g][i * 2 + 1], hh.y);
                    }
                }
            }
        }

        // Reduce over kg (lane bits 0..2) via butterfly shuffles
        float s[3][4];
#pragma unroll
        for (int g = 0; g < 3; g++)
#pragma unroll
            for (int b = 0; b < 4; b++) {
                float2 a = unpk(acc[g][b]);
                s[g][b] = a.x + a.y;
            }
#pragma unroll
        for (int o = 1; o < 8; o <<= 1)
#pragma unroll
            for (int g = 0; g < 3; g++)
#pragma unroll
                for (int b = 0; b < 4; b++)
                    s[g][b] += __shfl_xor_sync(0xFFFFFFFFu, s[g][b], o);
        if ((tid & 7) == 0) {
#pragma unroll
            for (int g = 0; g < 3; g++)
#pragma unroll
                for (int b = 0; b < 4; b++)
                    sout[g][b][rg] = s[g][b];
        }
        __syncthreads();

        if (tid < 128) {
            const float sr = sout[0][pb][pj];
            const float sz = sout[1][pb][pj];
            const float sn = sout[2][pb][pj];
            // torch GRU: n = tanh(xn + r*(hn + bhh_n))
            const float rg_ = 1.0f / (1.0f + __expf(-(xrv + sr + bh_r)));
            const float zg_ = 1.0f / (1.0f + __expf(-(xzv + sz + bh_z)));
            const float ng_ = tanhf(xnv + rg_ * (sn + bh_n));
            const float hnew = (1.0f - zg_) * ng_ + zg_ * h_prev;
            h_prev = hnew;
            // Publish h slice to double buffer (plain STG; ordered by bar+release)
            d_hbuf[((t & 1) * BG + bg) * HID * 4 + u * 4 + pb] = hnew;
            fcred[pb][pj] = fw * hnew;
        }
        __syncthreads();

        if (tid < 4) {                     // fc partial for our 32 units x batch tid
            float fs = 0.0f;
#pragma unroll
            for (int j = 0; j < 32; j++) fs += fcred[tid][j];
            d_fcp[((size_t)(bg * HG + hg) * SEQ + t) * 4 + tid] = fs;
        }
        __syncthreads();
        if (tid == 0)
            asm volatile("st.release.gpu.global.u32 [%0], %1;"
                         :: "l"(&d_tag[c * 8]), "r"((unsigned)(t + 1)) : "memory");
    }
}

// ---------------------------------------------------------------------------
// Kernel C: out[s][b] = fc_b + sum_hg fcp[bg(b)*8+hg][s][b&3]; re-arms tags.
// ---------------------------------------------------------------------------
__global__ void __launch_bounds__(512) final_kernel(const float* __restrict__ fc_b,
                                                    float* __restrict__ out) {
    const int idx = blockIdx.x * 512 + threadIdx.x;
    if (blockIdx.x == 0 && threadIdx.x < NCTA) d_tag[threadIdx.x * 8] = 0u;
    if (idx >= SEQ * BATCH) return;
    const int s  = idx >> 6;
    const int b6 = idx & 63;
    const int bg = b6 >> 2;
    const int bl = b6 & 3;
    float sum = fc_b[0];
#pragma unroll
    for (int hg = 0; hg < HG; hg++)
        sum += d_fcp[((size_t)(bg * HG + hg) * SEQ + s) * 4 + bl];
    out[idx] = sum;
}

extern "C" void kernel_launch(void* const* d_in, const int* in_sizes, int n_in,
                              void* d_out, int out_size) {
    const float* x    = (const float*)d_in[0];
    const float* w_ih = (const float*)d_in[1];
    const float* w_hh = (const float*)d_in[2];
    const float* b_ih = (const float*)d_in[3];
    const float* b_hh = (const float*)d_in[4];
    const float* fc_w = (const float*)d_in[5];
    const float* fc_b = (const float*)d_in[6];
    float* out = (float*)d_out;

    dim3 ga(SEQ, G3 / 64);
    xg_kernel<<<ga, 256>>>(x, w_ih, b_ih);                 // input projections
    scan_kernel<<<NCTA, 256>>>(w_hh, b_hh, fc_w);          // batch-tiled scan
    final_kernel<<<(SEQ * BATCH + 511) / 512, 512>>>(fc_b, out);
}